// round 17
// baseline (speedup 1.0000x reference)
#include <cuda_runtime.h>
#include <cstdint>

// EdgeBlock: out = LN( relu( [n[s]; n[r]; e] @ W1 + b1 ) @ W2 + b2 )
// R17 = R16 (CTA_M=64, warp grid 2(M)x4(N), 3 CTAs/SM, raw-fp32 A into tf32
// MMA, bulk-copied prepacked B) + TRIPLE-buffered A gather: A(ch+2) issued
// each chunk, cp.async.wait_group 1 at chunk top -> 2-chunk prefetch cover
// for the scattered gather instead of 1. A bufs (3 x 2304 fl) still alias H.
//
// CTA = 64 edges, 256 threads, 8 warps 2(M)x4(N), warp tile 32x32.
// GEMM1: K=384, 12 chunks of 32. GEMM2: K=128, 4 chunks of 32 (W2 streamed).

#define CTA_M   64
#define THREADS 256

#define A_STR  36
#define H_STR  132
#define B_CHUNK_FL 4224   // 32 blocks * 132 floats
#define B_CHUNK_BYTES (B_CHUNK_FL * 4)   // 16896

// smem float offsets
#define OFF_H    0        // [64][132] = 8448 (phase 2)
#define OFF_A0   0        // [64][36] = 2304 (phase 1, aliases H)
#define OFF_A1   2304
#define OFF_A2   4608     // ends 6912 (< 8448)
#define OFF_B0   8448     // 4224
#define OFF_B1   12672    // ends 16896
#define OFF_PRM  16896    // b1,b2,gamma,beta (512)
#define OFF_PS   17408    // LN partials: sums[4][64] + sqs[4][64] (512)
#define OFF_MBAR 17920    // 2 mbarriers (16 bytes)
#define SMEM_FLOATS 17928
#define SMEM_BYTES  (SMEM_FLOATS * 4)    // 71712 -> 3 CTAs/SM

__device__ uint32_t g_W1p[12 * B_CHUNK_FL];
__device__ uint32_t g_W2p[4 * B_CHUNK_FL];

__device__ __forceinline__ uint32_t f2tf(float f) {
    uint32_t u;
    asm("cvt.rna.tf32.f32 %0, %1;" : "=r"(u) : "f"(f));
    return u;
}
__device__ __forceinline__ uint32_t smem_u32(const void* p) {
    uint32_t a;
    asm("{ .reg .u64 t; cvta.to.shared.u64 t, %1; cvt.u32.u64 %0, t; }" : "=r"(a) : "l"(p));
    return a;
}
__device__ __forceinline__ void cp16(uint32_t dst, const void* src) {
    asm volatile("cp.async.cg.shared.global [%0], [%1], 16;" :: "r"(dst), "l"(src));
}
#define CP_COMMIT() asm volatile("cp.async.commit_group;" ::: "memory")
#define CP_WAIT0()  asm volatile("cp.async.wait_group 0;" ::: "memory")
#define CP_WAIT1()  asm volatile("cp.async.wait_group 1;" ::: "memory")

#define MBAR_INIT(mbar, cnt) \
    asm volatile("mbarrier.init.shared.b64 [%0], %1;" :: "r"((uint32_t)(mbar)), "r"((uint32_t)(cnt)) : "memory")
#define MBAR_ARRIVE_EXPECT(mbar, bytes) \
    asm volatile("mbarrier.arrive.expect_tx.shared.b64 _, [%0], %1;" :: "r"((uint32_t)(mbar)), "r"((uint32_t)(bytes)) : "memory")
#define BULK_G2S(dst, src, bytes, mbar) \
    asm volatile("cp.async.bulk.shared::cta.global.mbarrier::complete_tx::bytes [%0], [%1], %2, [%3];" \
                 :: "r"((uint32_t)(dst)), "l"(src), "r"((uint32_t)(bytes)), "r"((uint32_t)(mbar)) : "memory")

#define MBAR_WAIT(mbar, parity) do { \
    uint32_t _m = (uint32_t)(mbar); \
    uint32_t _p = (uint32_t)(parity); \
    uint32_t _done; \
    asm volatile( \
        "{\n\t.reg .pred p;\n\t" \
        "mbarrier.try_wait.parity.acquire.cta.shared::cta.b64 p, [%1], %2;\n\t" \
        "selp.b32 %0, 1, 0, p;\n\t}" \
        : "=r"(_done) : "r"(_m), "r"(_p) : "memory"); \
    if (!_done) { \
        asm volatile( \
            "{\n\t.reg .pred P1;\n\t" \
            "WAIT_LOOP_%=:\n\t" \
            "mbarrier.try_wait.parity.acquire.cta.shared::cta.b64 P1, [%0], %1, 0x989680;\n\t" \
            "@P1 bra.uni WAIT_DONE_%=;\n\t" \
            "bra.uni WAIT_LOOP_%=;\n\t" \
            "WAIT_DONE_%=:\n\t}" \
            :: "r"(_m), "r"(_p) : "memory"); \
    } \
} while(0)

__device__ __forceinline__ void mma8(float* d,
                                     uint32_t a0, uint32_t a1, uint32_t a2, uint32_t a3,
                                     uint32_t b0, uint32_t b1) {
    asm volatile(
        "mma.sync.aligned.m16n8k8.row.col.f32.tf32.tf32.f32 "
        "{%0,%1,%2,%3}, {%4,%5,%6,%7}, {%8,%9}, {%0,%1,%2,%3};"
        : "+f"(d[0]), "+f"(d[1]), "+f"(d[2]), "+f"(d[3])
        : "r"(a0), "r"(a1), "r"(a2), "r"(a3), "r"(b0), "r"(b1));
}

// ---------------- prepass: permute + cvt weights (R11 fragment order) -------
__global__ void pack_weights(const float* __restrict__ W1, const float* __restrict__ W2) {
    int i = blockIdx.x * 256 + threadIdx.x;
    const float* src;
    uint32_t* dst;
    int k, n;
    if (i < 384 * 128) {
        k = i >> 7; n = i & 127; src = W1; dst = g_W1p;
    } else {
        int i2 = i - 384 * 128;
        if (i2 >= 128 * 128) return;
        k = i2 >> 7; n = i2 & 127; src = W2; dst = g_W2p;
    }
    const int chunk = k >> 5;
    const int kk    = k & 31;
    const int ks    = kk >> 3;
    const int tg    = kk & 3;
    const int p     = (kk >> 2) & 1;
    const int half  = n >> 6;
    const int g     = n & 7;
    const int j     = (n & 63) >> 3;
    const int dest  = chunk * B_CHUNK_FL +
                      ((ks * 2 + half) * 4 + tg) * 132 + g * 16 + j * 2 + p;
    dst[dest] = f2tf(src[(size_t)k * 128 + n]);
}

// ---------------- main kernel ----------------
__global__ __launch_bounds__(THREADS, 3)
void edge_block_mma(const float* __restrict__ node_attr,
                    const float* __restrict__ edge_attr,
                    const int*   __restrict__ senders,
                    const int*   __restrict__ receivers,
                    const float* __restrict__ b1,
                    const float* __restrict__ b2,
                    const float* __restrict__ ln_g,
                    const float* __restrict__ ln_b,
                    float* __restrict__ out,
                    int E)
{
    extern __shared__ float smem[];
    float* prm = smem + OFF_PRM;
    float* ps  = smem + OFF_PS;

    const uint32_t sbase = smem_u32(smem);
    const uint32_t mb0 = sbase + OFF_MBAR * 4u;
    const uint32_t mb1 = mb0 + 8u;

    const int tid  = threadIdx.x;
    const int lane = tid & 31;
    const int wid  = tid >> 5;
    const int g    = lane >> 2;
    const int tig  = lane & 3;
    const int wm   = (wid >> 2) * 32;   // 2 M-warps x 32 rows
    const int wn   = (wid & 3) * 32;    // 4 N-warps x 32 cols
    const int wc   = wid & 3;
    const int eb   = blockIdx.x * CTA_M;

    if (tid < 128) {
        prm[tid]       = b1[tid];
        prm[128 + tid] = b2[tid];
        prm[256 + tid] = ln_g[tid];
        prm[384 + tid] = ln_b[tid];
    }
    if (tid == 0) { MBAR_INIT(mb0, 1); MBAR_INIT(mb1, 1); }

    // gather identity: 4 threads per row, 8 floats each
    const int arow = tid >> 2;          // 0..63
    const int aq   = tid & 3;
    int eg = eb + arow;
    if (eg >= E) eg = E - 1;
    const int sidx = senders[eg];
    const int ridx = receivers[eg];
    const float* base_s = node_attr + (size_t)sidx * 128;
    const float* base_r = node_attr + (size_t)ridx * 128;
    const float* base_e = edge_attr + (size_t)eg  * 128;

    const uint32_t offA[3] = {
        sbase + (OFF_A0 + arow * A_STR + aq * 8) * 4u,
        sbase + (OFF_A1 + arow * A_STR + aq * 8) * 4u,
        sbase + (OFF_A2 + arow * A_STR + aq * 8) * 4u };
    const uint32_t bdst[2] = { sbase + OFF_B0 * 4u, sbase + OFF_B1 * 4u };
    const uint32_t mbar[2] = { mb0, mb1 };

    auto issue_a = [&](int ch) {
        const uint32_t dst = offA[ch % 3];
        const int sel = ch >> 2;
        const float* ab = (sel == 0) ? base_s : ((sel == 1) ? base_r : base_e);
        const float* asrc = ab + (ch & 3) * 32 + aq * 8;
        cp16(dst, asrc);
        cp16(dst + 16, asrc + 4);
        CP_COMMIT();
    };

    __syncthreads();   // mbarrier init + prm visible

    float acc[2][4][4];
    #pragma unroll
    for (int i = 0; i < 2; ++i)
        #pragma unroll
        for (int j = 0; j < 4; ++j)
            #pragma unroll
            for (int c = 0; c < 4; ++c) acc[i][j][c] = 0.f;

    // prologue: A chunks 0,1 in flight; B chunk 0
    issue_a(0);
    issue_a(1);
    if (tid == 0) {
        MBAR_ARRIVE_EXPECT(mb0, B_CHUNK_BYTES);
        BULK_G2S(bdst[0], g_W1p, B_CHUNK_BYTES, mb0);
    }

    const int halfsel = wn >> 6;              // which 64-wide half
    const int jsel    = (wn & 32) >> 5;       // which j-quarter
    int ph0 = 0, ph1 = 0;

    // ======================= GEMM1: 12 chunks of k=32 =======================
    #pragma unroll 3
    for (int ch = 0; ch < 12; ++ch) {
        const int b = ch & 1;
        if (ch < 11) CP_WAIT1();   // A(ch) done; A(ch+1) may stay in flight
        else         CP_WAIT0();
        __syncthreads();           // A(ch) visible; chunk ch-1 reads done
        if (ch < 10) issue_a(ch + 2);   // buf (ch+2)%3: free since sync
        if (ch < 11) {
            if (tid == 0) {
                MBAR_ARRIVE_EXPECT(mbar[b ^ 1], B_CHUNK_BYTES);
                BULK_G2S(bdst[b ^ 1], g_W1p + (size_t)(ch + 1) * B_CHUNK_FL,
                         B_CHUNK_BYTES, mbar[b ^ 1]);
            }
        } else {
            if (tid == 0) {        // W2 chunk 0 -> buf0 (free: last read ch10)
                MBAR_ARRIVE_EXPECT(mb0, B_CHUNK_BYTES);
                BULK_G2S(bdst[0], g_W2p, B_CHUNK_BYTES, mb0);
            }
        }
        if (b == 0) { MBAR_WAIT(mb0, ph0); ph0 ^= 1; }
        else        { MBAR_WAIT(mb1, ph1); ph1 ^= 1; }

        const uint32_t* Af = reinterpret_cast<const uint32_t*>(smem)
                             + (ch % 3 == 0 ? OFF_A0 : (ch % 3 == 1 ? OFF_A1 : OFF_A2))
                             + (wm + g) * A_STR;
        const uint4* Bq = reinterpret_cast<const uint4*>(smem + (b ? OFF_B1 : OFF_B0));
        #pragma unroll
        for (int ks = 0; ks < 4; ++ks) {
            const int ka = ks * 8 + tig;
            const uint4* bp = Bq + (size_t)((ks * 2 + halfsel) * 4 + tig) * 33
                              + g * 4 + jsel * 2;
            uint4 r0 = bp[0], r1 = bp[1];
            uint32_t av[2][4];
            #pragma unroll
            for (int i = 0; i < 2; ++i) {
                // raw fp32 bits; tf32 MMA truncates in HW
                av[i][0] = Af[(16 * i)     * A_STR + ka];
                av[i][1] = Af[(16 * i + 8) * A_STR + ka];
                av[i][2] = Af[(16 * i)     * A_STR + ka + 4];
                av[i][3] = Af[(16 * i + 8) * A_STR + ka + 4];
            }
            #pragma unroll
            for (int i = 0; i < 2; ++i) {
                mma8(acc[i][0], av[i][0], av[i][1], av[i][2], av[i][3], r0.x, r0.y);
                mma8(acc[i][1], av[i][0], av[i][1], av[i][2], av[i][3], r0.z, r0.w);
                mma8(acc[i][2], av[i][0], av[i][1], av[i][2], av[i][3], r1.x, r1.y);
                mma8(acc[i][3], av[i][0], av[i][1], av[i][2], av[i][3], r1.z, r1.w);
            }
        }
    }
    __syncthreads();   // GEMM1 reads done; A region free for H

    // ---- H = relu(acc + b1) -> H[m][k] tf32 (uint2 pairs; W2(0) in flight)
    {
        uint32_t* Hsu = reinterpret_cast<uint32_t*>(smem + OFF_H);
        #pragma unroll
        for (int i = 0; i < 2; ++i) {
            const int r0 = wm + 16 * i + g;
            #pragma unroll
            for (int j = 0; j < 4; ++j) {
                const int n0 = wn + 8 * j + 2 * tig;
                float bj0 = prm[n0], bj1 = prm[n0 + 1];
                uint2 h01 = make_uint2(f2tf(fmaxf(acc[i][j][0] + bj0, 0.f)),
                                       f2tf(fmaxf(acc[i][j][1] + bj1, 0.f)));
                uint2 h23 = make_uint2(f2tf(fmaxf(acc[i][j][2] + bj0, 0.f)),
                                       f2tf(fmaxf(acc[i][j][3] + bj1, 0.f)));
                *reinterpret_cast<uint2*>(&Hsu[r0 * H_STR + n0])       = h01;
                *reinterpret_cast<uint2*>(&Hsu[(r0 + 8) * H_STR + n0]) = h23;
            }
        }
    }

    #pragma unroll
    for (int i = 0; i < 2; ++i)
        #pragma unroll
        for (int j = 0; j < 4; ++j)
            #pragma unroll
            for (int c = 0; c < 4; ++c) acc[i][j][c] = 0.f;

    // ======================= GEMM2: 4 chunks of k=32 =======================
    #pragma unroll 2
    for (int ch = 0; ch < 4; ++ch) {
        const int b = ch & 1;
        __syncthreads();          // H writes visible (ch0); prev buf reads done
        if (ch < 3 && tid == 0) {
            MBAR_ARRIVE_EXPECT(mbar[b ^ 1], B_CHUNK_BYTES);
            BULK_G2S(bdst[b ^ 1], g_W2p + (size_t)(ch + 1) * B_CHUNK_FL,
                     B_CHUNK_BYTES, mbar[b ^ 1]);
        }
        if (b == 0) { MBAR_WAIT(mb0, ph0); ph0 ^= 1; }
        else        { MBAR_WAIT(mb1, ph1); ph1 ^= 1; }

        const uint32_t* Hf = reinterpret_cast<const uint32_t*>(smem + OFF_H)
                             + (wm + g) * H_STR + ch * 32;
        const uint4* Bq = reinterpret_cast<const uint4*>(smem + (b ? OFF_B1 : OFF_B0));
        #pragma unroll
        for (int ks = 0; ks < 4; ++ks) {
            const int ka = ks * 8 + tig;
            const uint4* bp = Bq + (size_t)((ks * 2 + halfsel) * 4 + tig) * 33
                              + g * 4 + jsel * 2;
            uint4 r0 = bp[0], r1 = bp[1];
            uint32_t av[2][4];
            #pragma unroll
            for (int i = 0; i < 2; ++i) {
                av[i][0] = Hf[(16 * i)     * H_STR + ka];
                av[i][1] = Hf[(16 * i + 8) * H_STR + ka];
                av[i][2] = Hf[(16 * i)     * H_STR + ka + 4];
                av[i][3] = Hf[(16 * i + 8) * H_STR + ka + 4];
            }
            #pragma unroll
            for (int i = 0; i < 2; ++i) {
                mma8(acc[i][0], av[i][0], av[i][1], av[i][2], av[i][3], r0.x, r0.y);
                mma8(acc[i][1], av[i][0], av[i][1], av[i][2], av[i][3], r0.z, r0.w);
                mma8(acc[i][2], av[i][0], av[i][1], av[i][2], av[i][3], r1.x, r1.y);
                mma8(acc[i][3], av[i][0], av[i][1], av[i][2], av[i][3], r1.z, r1.w);
            }
        }
    }

    // ======================= LayerNorm epilogue (4 column partials) =========
    #pragma unroll
    for (int i = 0; i < 2; ++i) {
        float s0 = 0.f, q0 = 0.f, s1 = 0.f, q1 = 0.f;
        #pragma unroll
        for (int j = 0; j < 4; ++j) {
            const int n0 = wn + 8 * j + 2 * tig;
            float v0 = acc[i][j][0] + prm[128 + n0];
            float v1 = acc[i][j][1] + prm[128 + n0 + 1];
            float v2 = acc[i][j][2] + prm[128 + n0];
            float v3 = acc[i][j][3] + prm[128 + n0 + 1];
            acc[i][j][0] = v0; acc[i][j][1] = v1; acc[i][j][2] = v2; acc[i][j][3] = v3;
            s0 += v0 + v1; q0 += v0 * v0 + v1 * v1;
            s1 += v2 + v3; q1 += v2 * v2 + v3 * v3;
        }
        #pragma unroll
        for (int m = 1; m < 4; m <<= 1) {
            s0 += __shfl_xor_sync(0xffffffffu, s0, m);
            q0 += __shfl_xor_sync(0xffffffffu, q0, m);
            s1 += __shfl_xor_sync(0xffffffffu, s1, m);
            q1 += __shfl_xor_sync(0xffffffffu, q1, m);
        }
        if (tig == 0) {
            const int r0 = wm + 16 * i + g;
            ps[wc * 64 + r0]           = s0;
            ps[wc * 64 + r0 + 8]       = s1;
            ps[256 + wc * 64 + r0]     = q0;
            ps[256 + wc * 64 + r0 + 8] = q1;
        }
    }
    __syncthreads();

    #pragma unroll
    for (int i = 0; i < 2; ++i) {
        const int r0 = wm + 16 * i + g;
        const int r1 = r0 + 8;
        float s0 = ps[r0] + ps[64 + r0] + ps[128 + r0] + ps[192 + r0];
        float q0 = ps[256 + r0] + ps[320 + r0] + ps[384 + r0] + ps[448 + r0];
        float s1 = ps[r1] + ps[64 + r1] + ps[128 + r1] + ps[192 + r1];
        float q1 = ps[256 + r1] + ps[320 + r1] + ps[384 + r1] + ps[448 + r1];
        const float mu0 = s0 * (1.f / 128.f);
        const float mu1 = s1 * (1.f / 128.f);
        const float rs0 = rsqrtf(q0 * (1.f / 128.f) - mu0 * mu0 + 1e-5f);
        const float rs1 = rsqrtf(q1 * (1.f / 128.f) - mu1 * mu1 + 1e-5f);
        const int eg0 = eb + r0;
        const int eg1 = eb + r1;
        if (eg0 < E) {
            float* orow = out + (size_t)eg0 * 128;
            #pragma unroll
            for (int j = 0; j < 4; ++j) {
                const int n0 = wn + 8 * j + 2 * tig;
                float o0 = (acc[i][j][0] - mu0) * rs0 * prm[256 + n0]     + prm[384 + n0];
                float o1 = (acc[i][j][1] - mu0) * rs0 * prm[256 + n0 + 1] + prm[384 + n0 + 1];
                *reinterpret_cast<float2*>(orow + n0) = make_float2(o0, o1);
            }
        }
        if (eg1 < E) {
            float* orow = out + (size_t)eg1 * 128;
            #pragma unroll
            for (int j = 0; j < 4; ++j) {
                const int n0 = wn + 8 * j + 2 * tig;
                float o2 = (acc[i][j][2] - mu1) * rs1 * prm[256 + n0]     + prm[384 + n0];
                float o3 = (acc[i][j][3] - mu1) * rs1 * prm[256 + n0 + 1] + prm[384 + n0 + 1];
                *reinterpret_cast<float2*>(orow + n0) = make_float2(o2, o3);
            }
        }
    }
}

extern "C" void kernel_launch(void* const* d_in, const int* in_sizes, int n_in,
                              void* d_out, int out_size)
{
    (void)n_in; (void)out_size;
    const float* node_attr = (const float*)d_in[0];
    const float* edge_attr = (const float*)d_in[1];
    const int*   senders   = (const int*)  d_in[2];
    const int*   receivers = (const int*)  d_in[3];
    const float* W1        = (const float*)d_in[4];
    const float* b1        = (const float*)d_in[5];
    const float* W2        = (const float*)d_in[6];
    const float* b2        = (const float*)d_in[7];
    const float* ln_gamma  = (const float*)d_in[8];
    const float* ln_beta   = (const float*)d_in[9];
    float* out = (float*)d_out;

    const int E = in_sizes[2];

    pack_weights<<<256, 256>>>(W1, W2);

    cudaFuncSetAttribute(edge_block_mma,
                         cudaFuncAttributeMaxDynamicSharedMemorySize, SMEM_BYTES);

    const int grid = (E + CTA_M - 1) / CTA_M;
    edge_block_mma<<<grid, THREADS, SMEM_BYTES>>>(
        node_attr, edge_attr, senders, receivers,
        b1, b2, ln_gamma, ln_beta, out, E);
}